// round 1
// baseline (speedup 1.0000x reference)
#include <cuda_runtime.h>
#include <cuda_bf16.h>
#include <cstdint>

// Problem constants
#define ENT_GRID 16
#define ENT_DIM  64
#define EMB_DIM  1024   // ENT_GRID * ENT_DIM
#define LN_EPS   1e-5f

// Flag: 1 if proj_ids buffer is int64, 0 if int32. Set by detect kernel.
__device__ int g_ids_is64;

// Safe dtype sniffing: interpret the ids buffer as 32-bit words. If the true
// dtype is int64 (little-endian, values < 5000), every odd word of the buffer
// is 0. We only inspect the first n words (n = element count), which is
// in-bounds for BOTH interpretations (int32 buffer has n words, int64 has 2n).
// Odd words within the first n words = high halves of elements 0..n/2-1
// (int64 case) or elements 1,3,5,... (int32 case, random in [0,5000) -> not
// all zero with overwhelming probability).
__global__ void detect_ids_dtype_kernel(const int* __restrict__ w, int n_words) {
    __shared__ int any_nonzero;
    if (threadIdx.x == 0) any_nonzero = 0;
    __syncthreads();
    for (int i = 1 + 2 * threadIdx.x; i < n_words; i += 2 * blockDim.x) {
        if (w[i] != 0) any_nonzero = 1;
    }
    __syncthreads();
    if (threadIdx.x == 0) g_ids_is64 = (any_nonzero == 0) ? 1 : 0;
}

// One CTA (256 threads) per batch row.
// Thread t computes output rows r = t + 256*j, j=0..3.
__global__ __launch_bounds__(256, 8)
void wproj_ln_kernel(
    const float*     __restrict__ ent_emb,   // [B, 1024]
    const void*      __restrict__ proj_ids,  // [B] int32 or int64
    const float*     __restrict__ tran,      // [R, 64, 16, 16] -> [R, 1024, 16]
    const float*     __restrict__ bias,      // [R, 64, 16]     -> [R, 1024]
    const float*     __restrict__ ln_w,      // [1024]
    const float*     __restrict__ ln_b,      // [1024]
    float*           __restrict__ out)       // [B, 1024]
{
    const int b = blockIdx.x;
    const int t = threadIdx.x;

    __shared__ float4 e4[EMB_DIM / 4];   // 1024 floats of ent_emb row
    __shared__ float  red_s[8], red_s2[8];

    // Stage entity row into smem (coalesced float4 loads)
    const float4* erow = reinterpret_cast<const float4*>(ent_emb + (size_t)b * EMB_DIM);
    e4[t] = erow[t];
    __syncthreads();

    // Gather relation id
    long long rel;
    if (g_ids_is64) rel = reinterpret_cast<const long long*>(proj_ids)[b];
    else            rel = (long long)reinterpret_cast<const int*>(proj_ids)[b];

    const float* T  = tran + (size_t)rel * (EMB_DIM * ENT_GRID);  // 16384 floats
    const float* Bb = bias + (size_t)rel * EMB_DIM;

    float x[4];
    float s = 0.f, s2 = 0.f;

#pragma unroll
    for (int j = 0; j < 4; ++j) {
        const int r = t + j * 256;          // output row in [0,1024)
        const int d = r >> 4;               // which 16-block of e
        const float4* Trow = reinterpret_cast<const float4*>(T + (size_t)r * ENT_GRID);
        float acc = __ldg(Bb + r);
#pragma unroll
        for (int k = 0; k < 4; ++k) {
            const float4 tv = __ldg(Trow + k);
            const float4 ev = e4[d * 4 + k];
            acc += tv.x * ev.x + tv.y * ev.y + tv.z * ev.z + tv.w * ev.w;
        }
        x[j] = acc;
        s  += acc;
        s2 += acc * acc;
    }

    // Block reduction: warp shuffle then cross-warp via smem
#pragma unroll
    for (int o = 16; o > 0; o >>= 1) {
        s  += __shfl_xor_sync(0xffffffffu, s,  o);
        s2 += __shfl_xor_sync(0xffffffffu, s2, o);
    }
    const int wid = t >> 5, lid = t & 31;
    if (lid == 0) { red_s[wid] = s; red_s2[wid] = s2; }
    __syncthreads();
    if (wid == 0) {
        s  = (lid < 8) ? red_s[lid]  : 0.f;
        s2 = (lid < 8) ? red_s2[lid] : 0.f;
#pragma unroll
        for (int o = 4; o > 0; o >>= 1) {
            s  += __shfl_xor_sync(0xffffffffu, s,  o);
            s2 += __shfl_xor_sync(0xffffffffu, s2, o);
        }
        if (lid == 0) { red_s[0] = s; red_s2[0] = s2; }
    }
    __syncthreads();

    const float inv_n = 1.0f / (float)EMB_DIM;
    const float mean  = red_s[0] * inv_n;
    const float var   = red_s2[0] * inv_n - mean * mean;
    const float rstd  = rsqrtf(var + LN_EPS);

    float* ob = out + (size_t)b * EMB_DIM;
#pragma unroll
    for (int j = 0; j < 4; ++j) {
        const int r = t + j * 256;
        ob[r] = (x[j] - mean) * rstd * __ldg(ln_w + r) + __ldg(ln_b + r);
    }
}

extern "C" void kernel_launch(void* const* d_in, const int* in_sizes, int n_in,
                              void* d_out, int out_size) {
    const float* ent_emb = (const float*)d_in[0];
    const void*  ids     = d_in[1];
    const float* tran    = (const float*)d_in[2];
    const float* bias    = (const float*)d_in[3];
    const float* ln_w    = (const float*)d_in[4];
    const float* ln_b    = (const float*)d_in[5];
    float*       out     = (float*)d_out;

    const int batch = in_sizes[0] / EMB_DIM;   // 8192
    const int n_ids = in_sizes[1];             // element count of proj_ids

    detect_ids_dtype_kernel<<<1, 256>>>((const int*)ids, n_ids);
    wproj_ln_kernel<<<batch, 256>>>(ent_emb, ids, tran, bias, ln_w, ln_b, out);
}